// round 16
// baseline (speedup 1.0000x reference)
#include <cuda_runtime.h>
#include <cooperative_groups.h>

namespace cg = cooperative_groups;

// HyperMLP 128->512->512->512->128, per-sample weights streamed from z.
// 2-CTA cluster per sample, DSMEM push exchange (R8 structure).
// ReLU sparsity: ~50% of activations are exactly 0 -> their weight rows are
// never loaded (predicated ld.global.cs, zeros on skip — R11's proven form).
// R16 vs R11: (1) activation reads vectorized (one LDS.128 -> 4 xi -> 4
// predicated loads), breaking the per-row LDS->setp->LDG serial chain;
// (2) asm is non-volatile (pure load) so ptxas may batch the loads.

#define NBATCH 512
#define TOTAL_PARAMS 657024

#define W1_OFF 0          // 128*512
#define B1_OFF 65536      // 512
#define W2_OFF 66048      // 512*512
#define B2_OFF 328192     // 512
#define W3_OFF 328704     // 512*512
#define B3_OFF 590848     // 512
#define W4_OFF 591360     // 512*128
#define B4_OFF 656896     // 128

// Predicated streaming float4 load: returns *p if x != 0, else 0s.
// Non-volatile: pure function of (p, x); weights are never written.
__device__ __forceinline__ float4 ldcs_if(const float4* p, float x)
{
    float4 v;
    asm("{\n\t"
        ".reg .pred p;\n\t"
        "setp.ne.f32 p, %4, 0f00000000;\n\t"
        "mov.f32 %0, 0f00000000;\n\t"
        "mov.f32 %1, 0f00000000;\n\t"
        "mov.f32 %2, 0f00000000;\n\t"
        "mov.f32 %3, 0f00000000;\n\t"
        "@p ld.global.cs.v4.f32 {%0, %1, %2, %3}, [%5];\n\t"
        "}"
        : "=f"(v.x), "=f"(v.y), "=f"(v.z), "=f"(v.w)
        : "f"(x), "l"(p));
    return v;
}

__device__ __forceinline__ void fma4(float4& acc, float x, const float4& w)
{
    acc.x = fmaf(x, w.x, acc.x);
    acc.y = fmaf(x, w.y, acc.y);
    acc.z = fmaf(x, w.z, acc.z);
    acc.w = fmaf(x, w.w, acc.w);
}

__global__ __launch_bounds__(256, 8) __cluster_dims__(2, 1, 1)
void hypermlp_kernel(const float* __restrict__ z,
                     const float* __restrict__ xq,
                     float* __restrict__ out)
{
    cg::cluster_group cluster = cg::this_cluster();
    const int r    = (int)cluster.block_rank();   // 0 or 1
    const int peer = r ^ 1;
    const int b    = blockIdx.x >> 1;             // sample
    const float* __restrict__ zb = z + (size_t)b * TOTAL_PARAMS;
    const int t = threadIdx.x;                    // 0..255

    __shared__ float xs[2][512];                  // double-buffered activations
    __shared__ float red[1024];                   // 4KB partial-sum buffer

    float (*pxs)[512] = (float (*)[512])cluster.map_shared_rank(xs, peer);

    if (t < 128) xs[0][t] = xq[b * 128 + t];
    __syncthreads();

    const int o = r * 256 + t;                    // this thread's output index

    // ---------------- Layer 1: din=128 (dense input), dout=512 ----------------
    {
        const float4* __restrict__ wv = (const float4*)(zb + W1_OFF); // row=128 f4
        const int lane = t & 63;                  // 64 float4 = 256 outputs
        const int g    = t >> 6;                  // 4 groups x 32 i
        float4 acc = make_float4(0.f, 0.f, 0.f, 0.f);
        #pragma unroll 2
        for (int i0 = g * 32; i0 < g * 32 + 32; i0 += 4) {
            const float4 xv = *(const float4*)&xs[0][i0];   // one LDS.128
            fma4(acc, xv.x, __ldcs(&wv[(i0 + 0) * 128 + r * 64 + lane]));
            fma4(acc, xv.y, __ldcs(&wv[(i0 + 1) * 128 + r * 64 + lane]));
            fma4(acc, xv.z, __ldcs(&wv[(i0 + 2) * 128 + r * 64 + lane]));
            fma4(acc, xv.w, __ldcs(&wv[(i0 + 3) * 128 + r * 64 + lane]));
        }
        ((float4*)(red + g * 256))[lane] = acc;
        __syncthreads();
        float v = zb[B1_OFF + o];
        #pragma unroll
        for (int g2 = 0; g2 < 4; ++g2) v += red[g2 * 256 + t];
        v = fmaxf(v, 0.f);
        xs[1][o]  = v;
        pxs[1][o] = v;
        cluster.sync();
    }

    // ---------------- Layers 2 & 3: din=512 (relu-sparse), dout=512 -----------
    {
        const float* p = zb + W2_OFF;
        #pragma unroll 1
        for (int L = 0; L < 2; ++L) {
            const int cur = 1 - L;                // L2 reads buf1, L3 reads buf0
            const int nxt = L;
            const float4* __restrict__ wv = (const float4*)p;
            const float* __restrict__ bias = p + 512 * 512;
            const int lane = t & 63;
            const int g    = t >> 6;              // 4 groups x 128 i
            float4 acc = make_float4(0.f, 0.f, 0.f, 0.f);
            #pragma unroll 2
            for (int i0 = g * 128; i0 < g * 128 + 128; i0 += 4) {
                const float4 xv = *(const float4*)&xs[cur][i0];  // one LDS.128
                fma4(acc, xv.x, ldcs_if(&wv[(i0 + 0) * 128 + r * 64 + lane], xv.x));
                fma4(acc, xv.y, ldcs_if(&wv[(i0 + 1) * 128 + r * 64 + lane], xv.y));
                fma4(acc, xv.z, ldcs_if(&wv[(i0 + 2) * 128 + r * 64 + lane], xv.z));
                fma4(acc, xv.w, ldcs_if(&wv[(i0 + 3) * 128 + r * 64 + lane], xv.w));
            }
            ((float4*)(red + g * 256))[lane] = acc;
            __syncthreads();
            float v = bias[o];
            #pragma unroll
            for (int g2 = 0; g2 < 4; ++g2) v += red[g2 * 256 + t];
            v = fmaxf(v, 0.f);
            xs[nxt][o]  = v;
            pxs[nxt][o] = v;
            cluster.sync();
            p += 512 * 512 + 512;
        }
    }

    // ---------------- Layer 4: din=512 (relu-sparse), dout=128, no relu -------
    {
        const float4* __restrict__ wv = (const float4*)(zb + W4_OFF); // row=32 f4
        const int lane = t & 15;                  // 16 float4 = 64 outputs
        const int g    = t >> 4;                  // 16 groups x 32 i
        float4 acc = make_float4(0.f, 0.f, 0.f, 0.f);
        #pragma unroll 2
        for (int i0 = g * 32; i0 < g * 32 + 32; i0 += 4) {
            const float4 xv = *(const float4*)&xs[1][i0];
            fma4(acc, xv.x, ldcs_if(&wv[(i0 + 0) * 32 + r * 16 + lane], xv.x));
            fma4(acc, xv.y, ldcs_if(&wv[(i0 + 1) * 32 + r * 16 + lane], xv.y));
            fma4(acc, xv.z, ldcs_if(&wv[(i0 + 2) * 32 + r * 16 + lane], xv.z));
            fma4(acc, xv.w, ldcs_if(&wv[(i0 + 3) * 32 + r * 16 + lane], xv.w));
        }
        ((float4*)(red + g * 64))[lane] = acc;    // red as [16][64]
        __syncthreads();
        if (t < 64) {
            float v = zb[B4_OFF + r * 64 + t];
            #pragma unroll
            for (int g2 = 0; g2 < 16; ++g2) v += red[g2 * 64 + t];
            out[b * 128 + r * 64 + t] = v;
        }
    }
}

extern "C" void kernel_launch(void* const* d_in, const int* in_sizes, int n_in,
                              void* d_out, int out_size)
{
    const float* z  = (const float*)d_in[0];
    const float* xq = (const float*)d_in[1];
    if (n_in >= 2 && in_sizes[0] == NBATCH * 128) {
        z  = (const float*)d_in[1];
        xq = (const float*)d_in[0];
    }
    float* out = (float*)d_out;
    hypermlp_kernel<<<NBATCH * 2, 256>>>(z, xq, out);
}

// round 17
// speedup vs baseline: 1.1093x; 1.1093x over previous
#include <cuda_runtime.h>
#include <cooperative_groups.h>

namespace cg = cooperative_groups;

// HyperMLP 128->512->512->512->128, per-sample weights streamed from z.
// 2-CTA cluster per sample, DSMEM push exchange (R8 structure).
// ReLU sparsity: ~50% of activations are exactly 0. R17: warp-0 compacts
// the activation vector into a dense (idx,val) list once per layer; the
// sparse layers then iterate ONLY active rows with plain unpredicated
// __ldcs loads (no asm, fully batchable), perfectly balanced across groups.

#define NBATCH 512
#define TOTAL_PARAMS 657024

#define W1_OFF 0          // 128*512
#define B1_OFF 65536      // 512
#define W2_OFF 66048      // 512*512
#define B2_OFF 328192     // 512
#define W3_OFF 328704     // 512*512
#define B3_OFF 590848     // 512
#define W4_OFF 591360     // 512*128
#define B4_OFF 656896     // 128

__device__ __forceinline__ void fma4(float4& acc, float x, const float4& w)
{
    acc.x = fmaf(x, w.x, acc.x);
    acc.y = fmaf(x, w.y, acc.y);
    acc.z = fmaf(x, w.z, acc.z);
    acc.w = fmaf(x, w.w, acc.w);
}

__global__ __launch_bounds__(256, 8) __cluster_dims__(2, 1, 1)
void hypermlp_kernel(const float* __restrict__ z,
                     const float* __restrict__ xq,
                     float* __restrict__ out)
{
    cg::cluster_group cluster = cg::this_cluster();
    const int r    = (int)cluster.block_rank();   // 0 or 1
    const int peer = r ^ 1;
    const int b    = blockIdx.x >> 1;             // sample
    const float* __restrict__ zb = z + (size_t)b * TOTAL_PARAMS;
    const int t = threadIdx.x;                    // 0..255

    __shared__ float  xs[2][512];                 // double-buffered activations
    __shared__ float  red[1024];                  // 4KB partial-sum buffer
    __shared__ float2 nz[512];                    // compacted (idx_bits, val)
    __shared__ int    s_nnz;

    float (*pxs)[512] = (float (*)[512])cluster.map_shared_rank(xs, peer);

    if (t < 128) xs[0][t] = xq[b * 128 + t];
    __syncthreads();

    const int o = r * 256 + t;                    // this thread's output index

    // ---------------- Layer 1: din=128 (dense input), dout=512 ----------------
    {
        const float4* __restrict__ wv = (const float4*)(zb + W1_OFF); // row=128 f4
        const int lane = t & 63;                  // 64 float4 = 256 outputs
        const int g    = t >> 6;                  // 4 groups x 32 i
        float4 acc = make_float4(0.f, 0.f, 0.f, 0.f);
        #pragma unroll 8
        for (int i = g * 32; i < g * 32 + 32; ++i) {
            const float xi = xs[0][i];
            fma4(acc, xi, __ldcs(&wv[i * 128 + r * 64 + lane]));
        }
        ((float4*)(red + g * 256))[lane] = acc;
        __syncthreads();
        float v = zb[B1_OFF + o];
        #pragma unroll
        for (int g2 = 0; g2 < 4; ++g2) v += red[g2 * 256 + t];
        v = fmaxf(v, 0.f);
        xs[1][o]  = v;
        pxs[1][o] = v;
        cluster.sync();
    }

    // ---------------- Layers 2 & 3: din=512 (relu-sparse), dout=512 -----------
    {
        const float* p = zb + W2_OFF;
        #pragma unroll 1
        for (int L = 0; L < 2; ++L) {
            const int cur = 1 - L;                // L2 reads buf1, L3 reads buf0
            const int nxt = L;

            // Warp 0: deterministic sequential ballot compaction of xs[cur].
            if (t < 32) {
                int cnt = 0;
                #pragma unroll
                for (int c = 0; c < 16; ++c) {
                    const int   e = c * 32 + t;
                    const float v = xs[cur][e];
                    const bool  a = (v != 0.f);
                    const unsigned m = __ballot_sync(0xFFFFFFFFu, a);
                    const int pos = cnt + __popc(m & ((1u << t) - 1u));
                    if (a) nz[pos] = make_float2(__int_as_float(e), v);
                    cnt += __popc(m);
                }
                if (t == 0) s_nnz = cnt;
            }
            __syncthreads();
            const int nnz = s_nnz;

            const float4* __restrict__ wv = (const float4*)p;
            const float* __restrict__ bias = p + 512 * 512;
            const int lane = t & 63;
            const int g    = t >> 6;              // 4 groups, perfect k-split
            const int q    = (nnz + 3) >> 2;
            const int k0   = g * q;
            const int k1   = min(k0 + q, nnz);
            float4 acc = make_float4(0.f, 0.f, 0.f, 0.f);
            #pragma unroll 4
            for (int k = k0; k < k1; ++k) {
                const float2 e  = nz[k];          // one LDS.64, broadcast
                const int    i  = __float_as_int(e.x);
                fma4(acc, e.y, __ldcs(&wv[i * 128 + r * 64 + lane]));
            }
            ((float4*)(red + g * 256))[lane] = acc;
            __syncthreads();
            float v = bias[o];
            #pragma unroll
            for (int g2 = 0; g2 < 4; ++g2) v += red[g2 * 256 + t];
            v = fmaxf(v, 0.f);
            xs[nxt][o]  = v;
            pxs[nxt][o] = v;
            cluster.sync();
            p += 512 * 512 + 512;
        }
    }

    // ---------------- Layer 4: din=512 (relu-sparse), dout=128, no relu -------
    {
        if (t < 32) {
            int cnt = 0;
            #pragma unroll
            for (int c = 0; c < 16; ++c) {
                const int   e = c * 32 + t;
                const float v = xs[1][e];
                const bool  a = (v != 0.f);
                const unsigned m = __ballot_sync(0xFFFFFFFFu, a);
                const int pos = cnt + __popc(m & ((1u << t) - 1u));
                if (a) nz[pos] = make_float2(__int_as_float(e), v);
                cnt += __popc(m);
            }
            if (t == 0) s_nnz = cnt;
        }
        __syncthreads();
        const int nnz = s_nnz;

        const float4* __restrict__ wv = (const float4*)(zb + W4_OFF); // row=32 f4
        const int lane = t & 15;                  // 16 float4 = 64 outputs
        const int g    = t >> 4;                  // 16 groups, perfect k-split
        const int q    = (nnz + 15) >> 4;
        const int k0   = g * q;
        const int k1   = min(k0 + q, nnz);
        float4 acc = make_float4(0.f, 0.f, 0.f, 0.f);
        #pragma unroll 4
        for (int k = k0; k < k1; ++k) {
            const float2 e = nz[k];
            const int    i = __float_as_int(e.x);
            fma4(acc, e.y, __ldcs(&wv[i * 32 + r * 16 + lane]));
        }
        ((float4*)(red + g * 64))[lane] = acc;    // red as [16][64]
        __syncthreads();
        if (t < 64) {
            float v = zb[B4_OFF + r * 64 + t];
            #pragma unroll
            for (int g2 = 0; g2 < 16; ++g2) v += red[g2 * 64 + t];
            out[b * 128 + r * 64 + t] = v;
        }
    }
}

extern "C" void kernel_launch(void* const* d_in, const int* in_sizes, int n_in,
                              void* d_out, int out_size)
{
    const float* z  = (const float*)d_in[0];
    const float* xq = (const float*)d_in[1];
    if (n_in >= 2 && in_sizes[0] == NBATCH * 128) {
        z  = (const float*)d_in[1];
        xq = (const float*)d_in[0];
    }
    float* out = (float*)d_out;
    hypermlp_kernel<<<NBATCH * 2, 256>>>(z, xq, out);
}